// round 15
// baseline (speedup 1.0000x reference)
#include <cuda_runtime.h>
#include <cstdint>

#define NN 4096
#define HS 104            // permuted h row stride (floats); conflict-free LDS.128
typedef unsigned long long ull;
typedef unsigned int uint32;

__device__ __align__(128) float  g_x[NN*66];
__device__ __align__(128) float  g_h[4UL*NN*HS];
__device__ __align__(128) float  g_f1[4*NN];
__device__ __align__(128) float2 g_pq[4*NN];
__device__ __align__(128) float4 g_jd[4*NN];
__device__ __align__(128) float  g_hcat[NN*264];
__device__ __align__(128) float  g_sub[NN*66];
__device__ __align__(128) float  g_u[NN*64];
__device__ __align__(128) float  g_part[16UL*NN*72];
__device__ __align__(128) unsigned g_mask[NN*128];

__device__ __forceinline__ void cpa16(void* d, const void* s){
    unsigned sd = (unsigned)__cvta_generic_to_shared(d);
    asm volatile("cp.async.ca.shared.global [%0],[%1],16;" :: "r"(sd), "l"(s));
}
#define CP_COMMIT() asm volatile("cp.async.commit_group;")
#define CP_WAIT0()  asm volatile("cp.async.wait_group 0;")

__device__ __forceinline__ uint32 to_tf32(float f){
    uint32 u; asm("cvt.rna.tf32.f32 %0, %1;" : "=r"(u) : "f"(f)); return u;
}
__device__ __forceinline__ void mma_tf32(float4& d, uint32 a0, uint32 a1, uint32 a2, uint32 a3,
                                         uint32 b0, uint32 b1){
    asm("mma.sync.aligned.m16n8k8.row.col.f32.tf32.tf32.f32 "
        "{%0,%1,%2,%3},{%4,%5,%6,%7},{%8,%9},{%0,%1,%2,%3};"
        : "+f"(d.x), "+f"(d.y), "+f"(d.z), "+f"(d.w)
        : "r"(a0), "r"(a1), "r"(a2), "r"(a3), "r"(b0), "r"(b1));
}

__global__ void __launch_bounds__(256) pack_mask_kernel(const int* __restrict__ adj, unsigned* __restrict__ mask){
    int idx = blockIdx.x*256 + threadIdx.x;
    const int4* p = (const int4*)(adj + (size_t)idx*32);
    unsigned m = 0;
#pragma unroll
    for (int q = 0; q < 8; q++){
        int4 v = p[q];
        m |= (v.x>0?1u:0u)<<(q*4+0); m |= (v.y>0?1u:0u)<<(q*4+1);
        m |= (v.z>0?1u:0u)<<(q*4+2); m |= (v.w>0?1u:0u)<<(q*4+3);
    }
    mask[idx] = m;
}

__global__ void __launch_bounds__(256) build_x1_kernel(const float* __restrict__ inputs, const float* __restrict__ hx, float* __restrict__ x){
    int idx = blockIdx.x*256 + threadIdx.x;
    if (idx >= NN*66) return;
    int i = idx/66, c = idx - i*66;
    x[idx] = (c < 2) ? inputs[i*2+c] : hx[i*64 + c-2];
}

// h = x @ W per head, stored PERMUTED: col c -> slot (c&7)*12 + (c>>3), row stride HS.
// col 66 = ones (denominator), cols 67..71 = 0. + f1/jd/pq epilogue.
template<int ROWS>
__global__ void __launch_bounds__(256) proj_kernel(const float* __restrict__ x, int Din,
    const float* __restrict__ W, const float* __restrict__ a1, const float* __restrict__ a2,
    float* __restrict__ ho, float* __restrict__ f1o, float2* __restrict__ pqo, float4* __restrict__ jdo)
{
    constexpr int PR = 256/ROWS;
    __shared__ float Ws[66*66];
    __shared__ float xs[ROWS*67];
    const int head = blockIdx.y;
    const int row0 = blockIdx.x*ROWS;
    const int tid = threadIdx.x;
    W += (size_t)head*Din*66; a1 += head*66; a2 += head*66;
    const int r = tid/PR, part = tid%PR;
    int c0, cnt;
    if (PR == 4){ c0 = (part<2)?part*17:34+(part-2)*16; cnt = (part<2)?17:16; }
    else        { c0 = (part<6)?part*9:54+(part-6)*6;   cnt = (part<6)?9:6; }
    float acc[17];
#pragma unroll
    for (int c = 0; c < 17; c++) acc[c] = 0.f;
    for (int k0 = 0; k0 < Din; k0 += 66){
        __syncthreads();
        for (int idx = tid; idx < 66*66; idx += 256) Ws[idx] = W[(size_t)k0*66 + idx];
        for (int idx = tid; idx < ROWS*66; idx += 256){
            int rr = idx/66, kk = idx - rr*66;
            xs[rr*67+kk] = x[(size_t)(row0+rr)*Din + k0 + kk];
        }
        __syncthreads();
        for (int kk = 0; kk < 66; kk++){
            float xv = xs[r*67+kk];
            const float* wr = Ws + kk*66 + c0;
#pragma unroll
            for (int c = 0; c < 17; c++) if (c < cnt) acc[c] += xv*wr[c];
        }
    }
    float p1 = 0.f, p2 = 0.f;
#pragma unroll
    for (int c = 0; c < 17; c++) if (c < cnt){ p1 += acc[c]*a1[c0+c]; p2 += acc[c]*a2[c0+c]; }
#pragma unroll
    for (int s = 1; s < PR; s <<= 1){
        p1 += __shfl_xor_sync(~0u, p1, s);
        p2 += __shfl_xor_sync(~0u, p2, s);
    }
    int row = row0 + r;
    if (part == 0){
        f1o[head*NN+row] = p1;
        pqo[head*NN+row] = make_float2(__expf(p1), __expf(0.2f*p1));
        jdo[head*NN+row] = make_float4(p2, __expf(p2), __expf(0.2f*p2), 0.f);
    }
    float* hr = ho + (size_t)(head*NN+row)*HS;
#pragma unroll
    for (int c = 0; c < 17; c++) if (c < cnt){
        int col = c0 + c;
        hr[(col&7)*12 + (col>>3)] = __uint_as_float(to_tf32(acc[c]));
    }
    if (part == PR-1){
        hr[2*12 + 8] = 1.0f;           // col 66 -> ones
#pragma unroll
        for (int col = 67; col < 72; col++) hr[(col&7)*12 + 8] = 0.f;
    }
}

// A-fragment weight (R9 form — verified fastest).
__device__ __forceinline__ uint32 wcalc(float f1r, float2 pq, const float4& jd, unsigned mx, unsigned my, int j){
    float xx = f1r + jd.x;
    float w = (xx > 0.f) ? pq.x*jd.y : pq.y*jd.z;
    unsigned wd = (j & 32) ? my : mx;
    w = ((wd >> (j & 31)) & 1u) ? w : 0.f;
    return __float_as_uint(w);
}

// tensor-core masked softmax-attention aggregation.
// 128 rows/block, 128 threads (4 warps), 32 rows per warp (two m16 tiles sharing B loads).
// B tile stored permuted: thread (g,tig) reads its 9 nt-values contiguously (2x LDS.128 + LDS.32).
__global__ void __launch_bounds__(128,3) agg_mma_kernel(const float* __restrict__ hb,
    const float* __restrict__ f1b, const float2* __restrict__ pqb, const float4* __restrict__ jdb,
    const unsigned* __restrict__ mask, float* __restrict__ partp, int T)
{
    __shared__ float h_B[2][64*HS];
    __shared__ float4 jd_s[2][64];
    const int head = blockIdx.z;
    const int row0 = blockIdx.x*128;
    const int tid = threadIdx.x;
    const int wid = tid>>5, lane = tid&31;
    const int g = lane>>2, tig = lane&3;
    const int t0 = blockIdx.y*T;
    const float* hsrc = hb + (size_t)head*NN*HS;
    const float4* jds = jdb + head*NN;
    const int rA = row0 + wid*32 + g;          // rows: rA, rA+8, rA+16, rA+24
    const float f1_0 = f1b[head*NN + rA];
    const float f1_1 = f1b[head*NN + rA + 8];
    const float f1_2 = f1b[head*NN + rA + 16];
    const float f1_3 = f1b[head*NN + rA + 24];
    const float2 pq0 = pqb[head*NN + rA];
    const float2 pq1 = pqb[head*NN + rA + 8];
    const float2 pq2 = pqb[head*NN + rA + 16];
    const float2 pq3 = pqb[head*NN + rA + 24];
    const uint2* mrow0 = (const uint2*)(mask + (size_t)rA*128);
    const uint2* mrow1 = (const uint2*)(mask + (size_t)(rA+8)*128);
    const uint2* mrow2 = (const uint2*)(mask + (size_t)(rA+16)*128);
    const uint2* mrow3 = (const uint2*)(mask + (size_t)(rA+24)*128);

    float4 accA[9], accB[9];
#pragma unroll
    for (int nt = 0; nt < 9; nt++){ accA[nt] = make_float4(0.f,0.f,0.f,0.f); accB[nt] = accA[nt]; }

    // prefetch chunk t0: 64 rows x 96 floats used = 24 float4 chunks/row = 1536 chunks
#pragma unroll
    for (int i = 0; i < 12; i++){
        int idx = tid + i*128;
        int jr = idx/24, c4 = idx - jr*24;
        cpa16(&h_B[0][jr*HS + c4*4], hsrc + (size_t)(t0*64 + jr)*HS + c4*4);
    }
    if (tid < 64) cpa16(&jd_s[0][tid], &jds[t0*64 + tid]);
    CP_COMMIT();
    uint2 m0 = mrow0[t0], m1 = mrow1[t0], m2 = mrow2[t0], m3 = mrow3[t0];
    CP_WAIT0();
    __syncthreads();

    int buf = 0;
    for (int tt = 0; tt < T; tt++){
        const int t = t0 + tt;
        const bool more = (tt + 1 < T);
        if (more){
#pragma unroll
            for (int i = 0; i < 12; i++){
                int idx = tid + i*128;
                int jr = idx/24, c4 = idx - jr*24;
                cpa16(&h_B[buf^1][jr*HS + c4*4], hsrc + (size_t)((t+1)*64 + jr)*HS + c4*4);
            }
            if (tid < 64) cpa16(&jd_s[buf^1][tid], &jds[(t+1)*64 + tid]);
            CP_COMMIT();
        }
        uint2 nm0, nm1, nm2, nm3;
        if (more){ nm0 = mrow0[t+1]; nm1 = mrow1[t+1]; nm2 = mrow2[t+1]; nm3 = mrow3[t+1]; }

#pragma unroll
        for (int ks = 0; ks < 8; ks++){
            const int j0 = ks*8 + tig, j1 = j0 + 4;
            const float4 jd0 = jd_s[buf][j0];
            const float4 jd1 = jd_s[buf][j1];
            uint32 a0 = wcalc(f1_0, pq0, jd0, m0.x, m0.y, j0);
            uint32 a1 = wcalc(f1_1, pq1, jd0, m1.x, m1.y, j0);
            uint32 a2 = wcalc(f1_0, pq0, jd1, m0.x, m0.y, j1);
            uint32 a3 = wcalc(f1_1, pq1, jd1, m1.x, m1.y, j1);
            uint32 a4 = wcalc(f1_2, pq2, jd0, m2.x, m2.y, j0);
            uint32 a5 = wcalc(f1_3, pq3, jd0, m3.x, m3.y, j0);
            uint32 a6 = wcalc(f1_2, pq2, jd1, m2.x, m2.y, j1);
            uint32 a7 = wcalc(f1_3, pq3, jd1, m3.x, m3.y, j1);
            const float* hb0 = &h_B[buf][(ks*8 + tig)*HS + g*12];
            const float* hb1 = hb0 + 4*HS;
            float4 pA = *(const float4*)hb0;
            float4 pB = *(const float4*)(hb0 + 4);
            float  pC = hb0[8];
            float4 qA = *(const float4*)hb1;
            float4 qB = *(const float4*)(hb1 + 4);
            float  qC = hb1[8];
#define MMA_NT(nt, b0f, b1f) \
            { uint32 b0 = __float_as_uint(b0f), b1 = __float_as_uint(b1f); \
              mma_tf32(accA[nt], a0, a1, a2, a3, b0, b1); \
              mma_tf32(accB[nt], a4, a5, a6, a7, b0, b1); }
            MMA_NT(0, pA.x, qA.x)
            MMA_NT(1, pA.y, qA.y)
            MMA_NT(2, pA.z, qA.z)
            MMA_NT(3, pA.w, qA.w)
            MMA_NT(4, pB.x, qB.x)
            MMA_NT(5, pB.y, qB.y)
            MMA_NT(6, pB.z, qB.z)
            MMA_NT(7, pB.w, qB.w)
            MMA_NT(8, pC,   qC)
#undef MMA_NT
        }
        if (more) CP_WAIT0();
        __syncthreads();
        buf ^= 1;
        if (more){ m0 = nm0; m1 = nm1; m2 = nm2; m3 = nm3; }
    }

    float* p0 = partp + (((size_t)head*gridDim.y + blockIdx.y)*NN + rA)*72;
    float* p1 = p0 + 8*72;
    float* p2 = p0 + 16*72;
    float* p3 = p0 + 24*72;
#pragma unroll
    for (int nt = 0; nt < 9; nt++){
        int c = nt*8 + 2*tig;
        if (c < 66){
            p0[c] = accA[nt].x; p1[c] = accA[nt].z;
            p2[c] = accB[nt].x; p3[c] = accB[nt].z;
            if (c + 1 < 66){
                p0[c+1] = accA[nt].y; p1[c+1] = accA[nt].w;
                p2[c+1] = accB[nt].y; p3[c+1] = accB[nt].w;
            }
        }
    }
    if (tig == 1){
        p0[66] = accA[8].x; p1[66] = accA[8].z;
        p2[66] = accB[8].x; p3[66] = accB[8].z;
    }
}

// combine S splits per head: out[row, head*66+c] = lrelu(num/den). blockDim = H*66.
__global__ void reduce_kernel(const float* __restrict__ part, int S,
                              float* __restrict__ out, int os)
{
    int i = blockIdx.x;
    int t = threadIdx.x;
    int h = t/66, c = t - h*66;
    const float* p = part + (((size_t)h*S)*NN + i)*72;
    float num = 0.f, den = 0.f;
    for (int s = 0; s < S; s++){
        num += p[c]; den += p[66];
        p += (size_t)NN*72;
    }
    float v = num/den;
    out[(size_t)i*os + h*66 + c] = fmaxf(v, 0.01f*v);
}

__global__ void __launch_bounds__(128) gate1_kernel(const float* __restrict__ sub,
    const float* __restrict__ hx, const float* __restrict__ W, const float* __restrict__ b,
    float* __restrict__ xout, float* __restrict__ uout)
{
    __shared__ float xs[66];
    int i = blockIdx.x, c = threadIdx.x;
    for (int k = c; k < 66; k += 128) xs[k] = sub[i*66+k];
    __syncthreads();
    float a = b[c];
    for (int k = 0; k < 66; k++) a += xs[k]*W[k*128+c];
    float v = 1.f/(1.f + __expf(-a));
    if (c < 64) xout[i*66 + 2 + c] = v*hx[i*64+c];
    else uout[i*64 + c - 64] = v;
}

__global__ void __launch_bounds__(64) final_kernel(const float* __restrict__ sub,
    const float* __restrict__ hx, const float* __restrict__ u,
    const float* __restrict__ W, const float* __restrict__ b, float* __restrict__ out)
{
    __shared__ float xs[66];
    int i = blockIdx.x, c = threadIdx.x;
    for (int k = c; k < 66; k += 64) xs[k] = sub[i*66+k];
    __syncthreads();
    float a = b[c];
    for (int k = 0; k < 66; k++) a += xs[k]*W[k*64+c];
    float t = tanhf(a);
    float uu = u[i*64+c];
    out[i*64+c] = uu*hx[i*64+c] + (1.f - uu)*t;
}

struct Ptrs {
    float *x,*h,*f1,*hcat,*sub,*u,*part;
    float2 *pq; float4 *jd; unsigned *mask;
};

static void run_subnet(const Ptrs& P, const float* W, const float* a1, const float* a2,
    const float* Wout, const float* ao1, const float* ao2)
{
    proj_kernel<64><<<dim3(64,4), 256>>>(P.x, 66, W, a1, a2, P.h, P.f1, P.pq, P.jd);
    agg_mma_kernel<<<dim3(32,4,4), 128>>>(P.h, P.f1, P.pq, P.jd, P.mask, P.part, 16);
    reduce_kernel<<<NN, 264>>>(P.part, 4, P.hcat, 264);
    proj_kernel<32><<<dim3(128,1), 256>>>(P.hcat, 264, Wout, ao1, ao2, P.h, P.f1, P.pq, P.jd);
    agg_mma_kernel<<<dim3(32,16,1), 128>>>(P.h, P.f1, P.pq, P.jd, P.mask, P.part, 4);
    reduce_kernel<<<NN, 66>>>(P.part, 16, P.sub, 66);
}

extern "C" void kernel_launch(void* const* d_in, const int* in_sizes, int n_in,
                              void* d_out, int out_size)
{
    const float* inputs = (const float*)d_in[0];
    const float* hx     = (const float*)d_in[1];
    const int*   adj    = (const int*)d_in[2];
    const float* m1_W   = (const float*)d_in[3];
    const float* m1_a1  = (const float*)d_in[4];
    const float* m1_a2  = (const float*)d_in[5];
    const float* m1_Wo  = (const float*)d_in[6];
    const float* m1_ao1 = (const float*)d_in[7];
    const float* m1_ao2 = (const float*)d_in[8];
    const float* m2_W   = (const float*)d_in[9];
    const float* m2_a1  = (const float*)d_in[10];
    const float* m2_a2  = (const float*)d_in[11];
    const float* m2_Wo  = (const float*)d_in[12];
    const float* m2_ao1 = (const float*)d_in[13];
    const float* m2_ao2 = (const float*)d_in[14];
    const float* g1_W   = (const float*)d_in[15];
    const float* g1_b   = (const float*)d_in[16];
    const float* g2_W   = (const float*)d_in[17];
    const float* g2_b   = (const float*)d_in[18];

    Ptrs P; void* t;
    cudaGetSymbolAddress(&t, g_x);    P.x = (float*)t;
    cudaGetSymbolAddress(&t, g_h);    P.h = (float*)t;
    cudaGetSymbolAddress(&t, g_f1);   P.f1 = (float*)t;
    cudaGetSymbolAddress(&t, g_pq);   P.pq = (float2*)t;
    cudaGetSymbolAddress(&t, g_jd);   P.jd = (float4*)t;
    cudaGetSymbolAddress(&t, g_hcat); P.hcat = (float*)t;
    cudaGetSymbolAddress(&t, g_sub);  P.sub = (float*)t;
    cudaGetSymbolAddress(&t, g_u);    P.u = (float*)t;
    cudaGetSymbolAddress(&t, g_part); P.part = (float*)t;
    cudaGetSymbolAddress(&t, g_mask); P.mask = (unsigned*)t;

    pack_mask_kernel<<<2048, 256>>>(adj, P.mask);
    build_x1_kernel<<<(NN*66+255)/256, 256>>>(inputs, hx, P.x);
    run_subnet(P, m1_W, m1_a1, m1_a2, m1_Wo, m1_ao1, m1_ao2);
    gate1_kernel<<<NN, 128>>>(P.sub, hx, g1_W, g1_b, P.x, P.u);
    run_subnet(P, m2_W, m2_a1, m2_a2, m2_Wo, m2_ao1, m2_ao2);
    final_kernel<<<NN, 64>>>(P.sub, hx, P.u, g2_W, g2_b, (float*)d_out);
}

// round 16
// speedup vs baseline: 1.0365x; 1.0365x over previous
#include <cuda_runtime.h>
#include <cstdint>

#define NN 4096
#define HS 104            // permuted h row stride (floats); conflict-free LDS.128
typedef unsigned long long ull;
typedef unsigned int uint32;

__device__ __align__(128) float  g_x[NN*66];
__device__ __align__(128) float  g_h[4UL*NN*HS];
__device__ __align__(128) float  g_f1[4*NN];
__device__ __align__(128) float2 g_pq[4*NN];
__device__ __align__(128) float4 g_jd[4*NN];
__device__ __align__(128) float  g_hcat[NN*264];
__device__ __align__(128) float  g_u[NN*64];
__device__ __align__(128) float  g_part[32UL*NN*72];
__device__ __align__(128) unsigned g_mask[NN*128];

__device__ __forceinline__ void cpa16(void* d, const void* s){
    unsigned sd = (unsigned)__cvta_generic_to_shared(d);
    asm volatile("cp.async.ca.shared.global [%0],[%1],16;" :: "r"(sd), "l"(s));
}
#define CP_COMMIT() asm volatile("cp.async.commit_group;")
#define CP_WAIT0()  asm volatile("cp.async.wait_group 0;")

__device__ __forceinline__ uint32 to_tf32(float f){
    uint32 u; asm("cvt.rna.tf32.f32 %0, %1;" : "=r"(u) : "f"(f)); return u;
}
__device__ __forceinline__ void mma_tf32(float4& d, uint32 a0, uint32 a1, uint32 a2, uint32 a3,
                                         uint32 b0, uint32 b1){
    asm("mma.sync.aligned.m16n8k8.row.col.f32.tf32.tf32.f32 "
        "{%0,%1,%2,%3},{%4,%5,%6,%7},{%8,%9},{%0,%1,%2,%3};"
        : "+f"(d.x), "+f"(d.y), "+f"(d.z), "+f"(d.w)
        : "r"(a0), "r"(a1), "r"(a2), "r"(a3), "r"(b0), "r"(b1));
}

__global__ void __launch_bounds__(256) pack_mask_kernel(const int* __restrict__ adj, unsigned* __restrict__ mask){
    int idx = blockIdx.x*256 + threadIdx.x;
    const int4* p = (const int4*)(adj + (size_t)idx*32);
    unsigned m = 0;
#pragma unroll
    for (int q = 0; q < 8; q++){
        int4 v = p[q];
        m |= (v.x>0?1u:0u)<<(q*4+0); m |= (v.y>0?1u:0u)<<(q*4+1);
        m |= (v.z>0?1u:0u)<<(q*4+2); m |= (v.w>0?1u:0u)<<(q*4+3);
    }
    mask[idx] = m;
}

__global__ void __launch_bounds__(256) build_x1_kernel(const float* __restrict__ inputs, const float* __restrict__ hx, float* __restrict__ x){
    int idx = blockIdx.x*256 + threadIdx.x;
    if (idx >= NN*66) return;
    int i = idx/66, c = idx - i*66;
    x[idx] = (c < 2) ? inputs[i*2+c] : hx[i*64 + c-2];
}

// h = x @ W per head, stored PERMUTED: col c -> slot (c&7)*12 + (c>>3), row stride HS.
// col 66 = ones (denominator), cols 67..71 = 0. + f1/jd/pq epilogue.
template<int ROWS>
__global__ void __launch_bounds__(256) proj_kernel(const float* __restrict__ x, int Din,
    const float* __restrict__ W, const float* __restrict__ a1, const float* __restrict__ a2,
    float* __restrict__ ho, float* __restrict__ f1o, float2* __restrict__ pqo, float4* __restrict__ jdo)
{
    constexpr int PR = 256/ROWS;
    __shared__ float Ws[66*66];
    __shared__ float xs[ROWS*67];
    const int head = blockIdx.y;
    const int row0 = blockIdx.x*ROWS;
    const int tid = threadIdx.x;
    W += (size_t)head*Din*66; a1 += head*66; a2 += head*66;
    const int r = tid/PR, part = tid%PR;
    int c0, cnt;
    if (PR == 4){ c0 = (part<2)?part*17:34+(part-2)*16; cnt = (part<2)?17:16; }
    else        { c0 = (part<6)?part*9:54+(part-6)*6;   cnt = (part<6)?9:6; }
    float acc[17];
#pragma unroll
    for (int c = 0; c < 17; c++) acc[c] = 0.f;
    for (int k0 = 0; k0 < Din; k0 += 66){
        __syncthreads();
        for (int idx = tid; idx < 66*66; idx += 256) Ws[idx] = W[(size_t)k0*66 + idx];
        for (int idx = tid; idx < ROWS*66; idx += 256){
            int rr = idx/66, kk = idx - rr*66;
            xs[rr*67+kk] = x[(size_t)(row0+rr)*Din + k0 + kk];
        }
        __syncthreads();
        for (int kk = 0; kk < 66; kk++){
            float xv = xs[r*67+kk];
            const float* wr = Ws + kk*66 + c0;
#pragma unroll
            for (int c = 0; c < 17; c++) if (c < cnt) acc[c] += xv*wr[c];
        }
    }
    float p1 = 0.f, p2 = 0.f;
#pragma unroll
    for (int c = 0; c < 17; c++) if (c < cnt){ p1 += acc[c]*a1[c0+c]; p2 += acc[c]*a2[c0+c]; }
#pragma unroll
    for (int s = 1; s < PR; s <<= 1){
        p1 += __shfl_xor_sync(~0u, p1, s);
        p2 += __shfl_xor_sync(~0u, p2, s);
    }
    int row = row0 + r;
    if (part == 0){
        f1o[head*NN+row] = p1;
        pqo[head*NN+row] = make_float2(__expf(p1), __expf(0.2f*p1));
        jdo[head*NN+row] = make_float4(p2, __expf(p2), __expf(0.2f*p2), 0.f);
    }
    float* hr = ho + (size_t)(head*NN+row)*HS;
#pragma unroll
    for (int c = 0; c < 17; c++) if (c < cnt){
        int col = c0 + c;
        hr[(col&7)*12 + (col>>3)] = __uint_as_float(to_tf32(acc[c]));
    }
    if (part == PR-1){
        hr[2*12 + 8] = 1.0f;           // col 66 -> ones
#pragma unroll
        for (int col = 67; col < 72; col++) hr[(col&7)*12 + 8] = 0.f;
    }
}

// A-fragment weight (R9 form — verified fastest).
__device__ __forceinline__ uint32 wcalc(float f1r, float2 pq, const float4& jd, unsigned mx, unsigned my, int j){
    float xx = f1r + jd.x;
    float w = (xx > 0.f) ? pq.x*jd.y : pq.y*jd.z;
    unsigned wd = (j & 32) ? my : mx;
    w = ((wd >> (j & 31)) & 1u) ? w : 0.f;
    return __float_as_uint(w);
}

// tensor-core masked softmax-attention aggregation. (R12 config — measured best)
// 128 rows/block, 128 threads (4 warps), 32 rows per warp (two m16 tiles sharing B loads).
__global__ void __launch_bounds__(128) agg_mma_kernel(const float* __restrict__ hb,
    const float* __restrict__ f1b, const float2* __restrict__ pqb, const float4* __restrict__ jdb,
    const unsigned* __restrict__ mask, float* __restrict__ partp, int T)
{
    __shared__ float h_B[2][64*HS];
    __shared__ float4 jd_s[2][64];
    const int head = blockIdx.z;
    const int row0 = blockIdx.x*128;
    const int tid = threadIdx.x;
    const int wid = tid>>5, lane = tid&31;
    const int g = lane>>2, tig = lane&3;
    const int t0 = blockIdx.y*T;
    const float* hsrc = hb + (size_t)head*NN*HS;
    const float4* jds = jdb + head*NN;
    const int rA = row0 + wid*32 + g;          // rows: rA, rA+8, rA+16, rA+24
    const float f1_0 = f1b[head*NN + rA];
    const float f1_1 = f1b[head*NN + rA + 8];
    const float f1_2 = f1b[head*NN + rA + 16];
    const float f1_3 = f1b[head*NN + rA + 24];
    const float2 pq0 = pqb[head*NN + rA];
    const float2 pq1 = pqb[head*NN + rA + 8];
    const float2 pq2 = pqb[head*NN + rA + 16];
    const float2 pq3 = pqb[head*NN + rA + 24];
    const uint2* mrow0 = (const uint2*)(mask + (size_t)rA*128);
    const uint2* mrow1 = (const uint2*)(mask + (size_t)(rA+8)*128);
    const uint2* mrow2 = (const uint2*)(mask + (size_t)(rA+16)*128);
    const uint2* mrow3 = (const uint2*)(mask + (size_t)(rA+24)*128);

    float4 accA[9], accB[9];
#pragma unroll
    for (int nt = 0; nt < 9; nt++){ accA[nt] = make_float4(0.f,0.f,0.f,0.f); accB[nt] = accA[nt]; }

#pragma unroll
    for (int i = 0; i < 12; i++){
        int idx = tid + i*128;
        int jr = idx/24, c4 = idx - jr*24;
        cpa16(&h_B[0][jr*HS + c4*4], hsrc + (size_t)(t0*64 + jr)*HS + c4*4);
    }
    if (tid < 64) cpa16(&jd_s[0][tid], &jds[t0*64 + tid]);
    CP_COMMIT();
    uint2 m0 = mrow0[t0], m1 = mrow1[t0], m2 = mrow2[t0], m3 = mrow3[t0];
    CP_WAIT0();
    __syncthreads();

    int buf = 0;
    for (int tt = 0; tt < T; tt++){
        const int t = t0 + tt;
        const bool more = (tt + 1 < T);
        if (more){
#pragma unroll
            for (int i = 0; i < 12; i++){
                int idx = tid + i*128;
                int jr = idx/24, c4 = idx - jr*24;
                cpa16(&h_B[buf^1][jr*HS + c4*4], hsrc + (size_t)((t+1)*64 + jr)*HS + c4*4);
            }
            if (tid < 64) cpa16(&jd_s[buf^1][tid], &jds[(t+1)*64 + tid]);
            CP_COMMIT();
        }
        uint2 nm0, nm1, nm2, nm3;
        if (more){ nm0 = mrow0[t+1]; nm1 = mrow1[t+1]; nm2 = mrow2[t+1]; nm3 = mrow3[t+1]; }

#pragma unroll
        for (int ks = 0; ks < 8; ks++){
            const int j0 = ks*8 + tig, j1 = j0 + 4;
            const float4 jd0 = jd_s[buf][j0];
            const float4 jd1 = jd_s[buf][j1];
            uint32 a0 = wcalc(f1_0, pq0, jd0, m0.x, m0.y, j0);
            uint32 a1 = wcalc(f1_1, pq1, jd0, m1.x, m1.y, j0);
            uint32 a2 = wcalc(f1_0, pq0, jd1, m0.x, m0.y, j1);
            uint32 a3 = wcalc(f1_1, pq1, jd1, m1.x, m1.y, j1);
            uint32 a4 = wcalc(f1_2, pq2, jd0, m2.x, m2.y, j0);
            uint32 a5 = wcalc(f1_3, pq3, jd0, m3.x, m3.y, j0);
            uint32 a6 = wcalc(f1_2, pq2, jd1, m2.x, m2.y, j1);
            uint32 a7 = wcalc(f1_3, pq3, jd1, m3.x, m3.y, j1);
            const float* hb0 = &h_B[buf][(ks*8 + tig)*HS + g*12];
            const float* hb1 = hb0 + 4*HS;
            float4 pA = *(const float4*)hb0;
            float4 pB = *(const float4*)(hb0 + 4);
            float  pC = hb0[8];
            float4 qA = *(const float4*)hb1;
            float4 qB = *(const float4*)(hb1 + 4);
            float  qC = hb1[8];
            float bl0[9] = {pA.x,pA.y,pA.z,pA.w, pB.x,pB.y,pB.z,pB.w, pC};
            float bl1[9] = {qA.x,qA.y,qA.z,qA.w, qB.x,qB.y,qB.z,qB.w, qC};
#pragma unroll
            for (int nt = 0; nt < 9; nt++){
                uint32 b0 = __float_as_uint(bl0[nt]);
                uint32 b1 = __float_as_uint(bl1[nt]);
                mma_tf32(accA[nt], a0, a1, a2, a3, b0, b1);
                mma_tf32(accB[nt], a4, a5, a6, a7, b0, b1);
            }
        }
        if (more) CP_WAIT0();
        __syncthreads();
        buf ^= 1;
        if (more){ m0 = nm0; m1 = nm1; m2 = nm2; m3 = nm3; }
    }

    float* p0 = partp + (((size_t)head*gridDim.y + blockIdx.y)*NN + rA)*72;
    float* p1 = p0 + 8*72;
    float* p2 = p0 + 16*72;
    float* p3 = p0 + 24*72;
#pragma unroll
    for (int nt = 0; nt < 9; nt++){
        int c = nt*8 + 2*tig;
        if (c < 66){
            p0[c] = accA[nt].x; p1[c] = accA[nt].z;
            p2[c] = accB[nt].x; p3[c] = accB[nt].z;
            if (c + 1 < 66){
                p0[c+1] = accA[nt].y; p1[c+1] = accA[nt].w;
                p2[c+1] = accB[nt].y; p3[c+1] = accB[nt].w;
            }
        }
    }
    if (tig == 1){
        p0[66] = accA[8].x; p1[66] = accA[8].z;
        p2[66] = accB[8].x; p3[66] = accB[8].z;
    }
}

// combine S splits per head: out[row, head*66+c] = lrelu(num/den). blockDim = H*66.
__global__ void reduce_kernel(const float* __restrict__ part, int S,
                              float* __restrict__ out, int os)
{
    int i = blockIdx.x;
    int t = threadIdx.x;
    int h = t/66, c = t - h*66;
    const float* p = part + (((size_t)h*S)*NN + i)*72;
    float num = 0.f, den = 0.f;
    for (int s = 0; s < S; s++){
        num += p[c]; den += p[66];
        p += (size_t)NN*72;
    }
    float v = num/den;
    out[(size_t)i*os + h*66 + c] = fmaxf(v, 0.01f*v);
}

// fused: reduce 16 stage-2 splits -> sub[66] in smem, then value=sigmoid(sub@W+b).
__global__ void __launch_bounds__(128) gate1_fused_kernel(const float* __restrict__ part,
    const float* __restrict__ hx, const float* __restrict__ W, const float* __restrict__ b,
    float* __restrict__ xout, float* __restrict__ uout)
{
    __shared__ float xs[66];
    int i = blockIdx.x, c = threadIdx.x;
    if (c < 66){
        const float* p = part + (size_t)i*72;
        float num = 0.f, den = 0.f;
#pragma unroll
        for (int s = 0; s < 16; s++){
            num += p[c]; den += p[66];
            p += (size_t)NN*72;
        }
        float v = num/den;
        xs[c] = fmaxf(v, 0.01f*v);
    }
    __syncthreads();
    float a = b[c];
    for (int k = 0; k < 66; k++) a += xs[k]*W[k*128+c];
    float v = 1.f/(1.f + __expf(-a));
    if (c < 64) xout[i*66 + 2 + c] = v*hx[i*64+c];
    else uout[i*64 + c - 64] = v;
}

// fused: reduce 16 stage-2 splits -> sub[66], then c=tanh(sub@W+b), out = u*hx + (1-u)*c.
__global__ void __launch_bounds__(128) final_fused_kernel(const float* __restrict__ part,
    const float* __restrict__ hx, const float* __restrict__ u,
    const float* __restrict__ W, const float* __restrict__ b, float* __restrict__ out)
{
    __shared__ float xs[66];
    int i = blockIdx.x, c = threadIdx.x;
    if (c < 66){
        const float* p = part + (size_t)i*72;
        float num = 0.f, den = 0.f;
#pragma unroll
        for (int s = 0; s < 16; s++){
            num += p[c]; den += p[66];
            p += (size_t)NN*72;
        }
        float v = num/den;
        xs[c] = fmaxf(v, 0.01f*v);
    }
    __syncthreads();
    if (c >= 64) return;
    float a = b[c];
    for (int k = 0; k < 66; k++) a += xs[k]*W[k*64+c];
    float t = tanhf(a);
    float uu = u[i*64+c];
    out[i*64+c] = uu*hx[i*64+c] + (1.f - uu)*t;
}

struct Ptrs {
    float *x,*h,*f1,*hcat,*u,*part;
    float2 *pq; float4 *jd; unsigned *mask;
};

static void run_subnet(const Ptrs& P, const float* W, const float* a1, const float* a2,
    const float* Wout, const float* ao1, const float* ao2)
{
    proj_kernel<64><<<dim3(64,4), 256>>>(P.x, 66, W, a1, a2, P.h, P.f1, P.pq, P.jd);
    agg_mma_kernel<<<dim3(32,8,4), 128>>>(P.h, P.f1, P.pq, P.jd, P.mask, P.part, 8);
    reduce_kernel<<<NN, 264>>>(P.part, 8, P.hcat, 264);
    proj_kernel<32><<<dim3(128,1), 256>>>(P.hcat, 264, Wout, ao1, ao2, P.h, P.f1, P.pq, P.jd);
    agg_mma_kernel<<<dim3(32,16,1), 128>>>(P.h, P.f1, P.pq, P.jd, P.mask, P.part, 4);
}

extern "C" void kernel_launch(void* const* d_in, const int* in_sizes, int n_in,
                              void* d_out, int out_size)
{
    const float* inputs = (const float*)d_in[0];
    const float* hx     = (const float*)d_in[1];
    const int*   adj    = (const int*)d_in[2];
    const float* m1_W   = (const float*)d_in[3];
    const float* m1_a1  = (const float*)d_in[4];
    const float* m1_a2  = (const float*)d_in[5];
    const float* m1_Wo  = (const float*)d_in[6];
    const float* m1_ao1 = (const float*)d_in[7];
    const float* m1_ao2 = (const float*)d_in[8];
    const float* m2_W   = (const float*)d_in[9];
    const float* m2_a1  = (const float*)d_in[10];
    const float* m2_a2  = (const float*)d_in[11];
    const float* m2_Wo  = (const float*)d_in[12];
    const float* m2_ao1 = (const float*)d_in[13];
    const float* m2_ao2 = (const float*)d_in[14];
    const float* g1_W   = (const float*)d_in[15];
    const float* g1_b   = (const float*)d_in[16];
    const float* g2_W   = (const float*)d_in[17];
    const float* g2_b   = (const float*)d_in[18];

    Ptrs P; void* t;
    cudaGetSymbolAddress(&t, g_x);    P.x = (float*)t;
    cudaGetSymbolAddress(&t, g_h);    P.h = (float*)t;
    cudaGetSymbolAddress(&t, g_f1);   P.f1 = (float*)t;
    cudaGetSymbolAddress(&t, g_pq);   P.pq = (float2*)t;
    cudaGetSymbolAddress(&t, g_jd);   P.jd = (float4*)t;
    cudaGetSymbolAddress(&t, g_hcat); P.hcat = (float*)t;
    cudaGetSymbolAddress(&t, g_u);    P.u = (float*)t;
    cudaGetSymbolAddress(&t, g_part); P.part = (float*)t;
    cudaGetSymbolAddress(&t, g_mask); P.mask = (unsigned*)t;

    pack_mask_kernel<<<2048, 256>>>(adj, P.mask);
    build_x1_kernel<<<(NN*66+255)/256, 256>>>(inputs, hx, P.x);
    run_subnet(P, m1_W, m1_a1, m1_a2, m1_Wo, m1_ao1, m1_ao2);
    gate1_fused_kernel<<<NN, 128>>>(P.part, hx, g1_W, g1_b, P.x, P.u);
    run_subnet(P, m2_W, m2_a1, m2_a2, m2_Wo, m2_ao1, m2_ao2);
    final_fused_kernel<<<NN, 128>>>(P.part, hx, P.u, g2_W, g2_b, (float*)d_out);
}

// round 17
// speedup vs baseline: 1.0505x; 1.0136x over previous
#include <cuda_runtime.h>
#include <cstdint>

#define NN 4096
#define HS 104            // permuted h row stride (floats); conflict-free LDS.128
typedef unsigned long long ull;
typedef unsigned int uint32;

__device__ __align__(128) float  g_x[NN*66];
__device__ __align__(128) float  g_h[4UL*NN*HS];
__device__ __align__(128) float  g_f1[4*NN];
__device__ __align__(128) float2 g_pq[4*NN];
__device__ __align__(128) float4 g_jd[4*NN];
__device__ __align__(128) float  g_hcat[NN*264];
__device__ __align__(128) float  g_u[NN*64];
__device__ __align__(128) float  g_part[32UL*NN*72];
__device__ __align__(128) unsigned g_mask[NN*128];

__device__ __forceinline__ void cpa16(void* d, const void* s){
    unsigned sd = (unsigned)__cvta_generic_to_shared(d);
    asm volatile("cp.async.ca.shared.global [%0],[%1],16;" :: "r"(sd), "l"(s));
}
#define CP_COMMIT() asm volatile("cp.async.commit_group;")
#define CP_WAIT0()  asm volatile("cp.async.wait_group 0;")

__device__ __forceinline__ uint32 to_tf32(float f){
    uint32 u; asm("cvt.rna.tf32.f32 %0, %1;" : "=r"(u) : "f"(f)); return u;
}
__device__ __forceinline__ void mma_tf32(float4& d, uint32 a0, uint32 a1, uint32 a2, uint32 a3,
                                         uint32 b0, uint32 b1){
    asm("mma.sync.aligned.m16n8k8.row.col.f32.tf32.tf32.f32 "
        "{%0,%1,%2,%3},{%4,%5,%6,%7},{%8,%9},{%0,%1,%2,%3};"
        : "+f"(d.x), "+f"(d.y), "+f"(d.z), "+f"(d.w)
        : "r"(a0), "r"(a1), "r"(a2), "r"(a3), "r"(b0), "r"(b1));
}

__global__ void __launch_bounds__(256) pack_mask_kernel(const int* __restrict__ adj, unsigned* __restrict__ mask){
    int idx = blockIdx.x*256 + threadIdx.x;
    const int4* p = (const int4*)(adj + (size_t)idx*32);
    unsigned m = 0;
#pragma unroll
    for (int q = 0; q < 8; q++){
        int4 v = p[q];
        m |= (v.x>0?1u:0u)<<(q*4+0); m |= (v.y>0?1u:0u)<<(q*4+1);
        m |= (v.z>0?1u:0u)<<(q*4+2); m |= (v.w>0?1u:0u)<<(q*4+3);
    }
    mask[idx] = m;
}

__global__ void __launch_bounds__(256) build_x1_kernel(const float* __restrict__ inputs, const float* __restrict__ hx, float* __restrict__ x){
    int idx = blockIdx.x*256 + threadIdx.x;
    if (idx >= NN*66) return;
    int i = idx/66, c = idx - i*66;
    x[idx] = (c < 2) ? inputs[i*2+c] : hx[i*64 + c-2];
}

// h = x @ W per head, stored PERMUTED: col c -> slot (c&7)*12 + (c>>3), row stride HS.
// col 66 = ones (denominator), cols 67..71 = 0. + f1/jd/pq epilogue.
// PR parts per row (power of 2), RPT rows per thread. 256 threads.
template<int PR, int RPT>
__global__ void __launch_bounds__(256) proj_kernel(const float* __restrict__ x, int Din,
    const float* __restrict__ W, const float* __restrict__ a1, const float* __restrict__ a2,
    float* __restrict__ ho, float* __restrict__ f1o, float2* __restrict__ pqo, float4* __restrict__ jdo)
{
    constexpr int GROUPS = 256/PR;
    constexpr int ROWS = GROUPS*RPT;
    constexpr int BASE = 66/PR, REM = 66%PR;
    constexpr int MAXC = BASE + 1;
    __shared__ float Ws[66*66];
    __shared__ float xs[ROWS*67];
    const int head = blockIdx.y;
    const int row0 = blockIdx.x*ROWS;
    const int tid = threadIdx.x;
    W += (size_t)head*Din*66; a1 += head*66; a2 += head*66;
    const int grp = tid/PR, part = tid%PR;
    const int c0 = part*BASE + (part < REM ? part : REM);
    const int cnt = BASE + (part < REM ? 1 : 0);
    float acc[RPT][MAXC];
#pragma unroll
    for (int rr = 0; rr < RPT; rr++)
#pragma unroll
        for (int c = 0; c < MAXC; c++) acc[rr][c] = 0.f;
    for (int k0 = 0; k0 < Din; k0 += 66){
        __syncthreads();
        for (int idx = tid; idx < 66*66; idx += 256) Ws[idx] = W[(size_t)k0*66 + idx];
        for (int idx = tid; idx < ROWS*66; idx += 256){
            int rr = idx/66, kk = idx - rr*66;
            xs[rr*67+kk] = x[(size_t)(row0+rr)*Din + k0 + kk];
        }
        __syncthreads();
        for (int kk = 0; kk < 66; kk++){
            float xv[RPT];
#pragma unroll
            for (int rr = 0; rr < RPT; rr++) xv[rr] = xs[(grp*RPT+rr)*67 + kk];
            const float* wr = Ws + kk*66 + c0;
#pragma unroll
            for (int c = 0; c < MAXC; c++) if (c < cnt){
                float wv = wr[c];
#pragma unroll
                for (int rr = 0; rr < RPT; rr++) acc[rr][c] += xv[rr]*wv;
            }
        }
    }
    float p1[RPT], p2[RPT];
#pragma unroll
    for (int rr = 0; rr < RPT; rr++){ p1[rr] = 0.f; p2[rr] = 0.f; }
#pragma unroll
    for (int c = 0; c < MAXC; c++) if (c < cnt){
        float v1 = a1[c0+c], v2 = a2[c0+c];
#pragma unroll
        for (int rr = 0; rr < RPT; rr++){ p1[rr] += acc[rr][c]*v1; p2[rr] += acc[rr][c]*v2; }
    }
#pragma unroll
    for (int s = 1; s < PR; s <<= 1){
#pragma unroll
        for (int rr = 0; rr < RPT; rr++){
            p1[rr] += __shfl_xor_sync(~0u, p1[rr], s);
            p2[rr] += __shfl_xor_sync(~0u, p2[rr], s);
        }
    }
#pragma unroll
    for (int rr = 0; rr < RPT; rr++){
        int row = row0 + grp*RPT + rr;
        if (part == 0){
            f1o[head*NN+row] = p1[rr];
            pqo[head*NN+row] = make_float2(__expf(p1[rr]), __expf(0.2f*p1[rr]));
            jdo[head*NN+row] = make_float4(p2[rr], __expf(p2[rr]), __expf(0.2f*p2[rr]), 0.f);
        }
        float* hr = ho + (size_t)(head*NN+row)*HS;
#pragma unroll
        for (int c = 0; c < MAXC; c++) if (c < cnt){
            int col = c0 + c;
            hr[(col&7)*12 + (col>>3)] = __uint_as_float(to_tf32(acc[rr][c]));
        }
        if (part == PR-1){
            hr[2*12 + 8] = 1.0f;           // col 66 -> ones
#pragma unroll
            for (int col = 67; col < 72; col++) hr[(col&7)*12 + 8] = 0.f;
        }
    }
}

// A-fragment weight (R9 form — verified fastest).
__device__ __forceinline__ uint32 wcalc(float f1r, float2 pq, const float4& jd, unsigned mx, unsigned my, int j){
    float xx = f1r + jd.x;
    float w = (xx > 0.f) ? pq.x*jd.y : pq.y*jd.z;
    unsigned wd = (j & 32) ? my : mx;
    w = ((wd >> (j & 31)) & 1u) ? w : 0.f;
    return __float_as_uint(w);
}

// tensor-core masked softmax-attention aggregation. (R12 config — measured best)
// 128 rows/block, 128 threads (4 warps), 32 rows per warp (two m16 tiles sharing B loads).
__global__ void __launch_bounds__(128) agg_mma_kernel(const float* __restrict__ hb,
    const float* __restrict__ f1b, const float2* __restrict__ pqb, const float4* __restrict__ jdb,
    const unsigned* __restrict__ mask, float* __restrict__ partp, int T)
{
    __shared__ float h_B[2][64*HS];
    __shared__ float4 jd_s[2][64];
    const int head = blockIdx.z;
    const int row0 = blockIdx.x*128;
    const int tid = threadIdx.x;
    const int wid = tid>>5, lane = tid&31;
    const int g = lane>>2, tig = lane&3;
    const int t0 = blockIdx.y*T;
    const float* hsrc = hb + (size_t)head*NN*HS;
    const float4* jds = jdb + head*NN;
    const int rA = row0 + wid*32 + g;          // rows: rA, rA+8, rA+16, rA+24
    const float f1_0 = f1b[head*NN + rA];
    const float f1_1 = f1b[head*NN + rA + 8];
    const float f1_2 = f1b[head*NN + rA + 16];
    const float f1_3 = f1b[head*NN + rA + 24];
    const float2 pq0 = pqb[head*NN + rA];
    const float2 pq1 = pqb[head*NN + rA + 8];
    const float2 pq2 = pqb[head*NN + rA + 16];
    const float2 pq3 = pqb[head*NN + rA + 24];
    const uint2* mrow0 = (const uint2*)(mask + (size_t)rA*128);
    const uint2* mrow1 = (const uint2*)(mask + (size_t)(rA+8)*128);
    const uint2* mrow2 = (const uint2*)(mask + (size_t)(rA+16)*128);
    const uint2* mrow3 = (const uint2*)(mask + (size_t)(rA+24)*128);

    float4 accA[9], accB[9];
#pragma unroll
    for (int nt = 0; nt < 9; nt++){ accA[nt] = make_float4(0.f,0.f,0.f,0.f); accB[nt] = accA[nt]; }

#pragma unroll
    for (int i = 0; i < 12; i++){
        int idx = tid + i*128;
        int jr = idx/24, c4 = idx - jr*24;
        cpa16(&h_B[0][jr*HS + c4*4], hsrc + (size_t)(t0*64 + jr)*HS + c4*4);
    }
    if (tid < 64) cpa16(&jd_s[0][tid], &jds[t0*64 + tid]);
    CP_COMMIT();
    uint2 m0 = mrow0[t0], m1 = mrow1[t0], m2 = mrow2[t0], m3 = mrow3[t0];
    CP_WAIT0();
    __syncthreads();

    int buf = 0;
    for (int tt = 0; tt < T; tt++){
        const int t = t0 + tt;
        const bool more = (tt + 1 < T);
        if (more){
#pragma unroll
            for (int i = 0; i < 12; i++){
                int idx = tid + i*128;
                int jr = idx/24, c4 = idx - jr*24;
                cpa16(&h_B[buf^1][jr*HS + c4*4], hsrc + (size_t)((t+1)*64 + jr)*HS + c4*4);
            }
            if (tid < 64) cpa16(&jd_s[buf^1][tid], &jds[(t+1)*64 + tid]);
            CP_COMMIT();
        }
        uint2 nm0, nm1, nm2, nm3;
        if (more){ nm0 = mrow0[t+1]; nm1 = mrow1[t+1]; nm2 = mrow2[t+1]; nm3 = mrow3[t+1]; }

#pragma unroll
        for (int ks = 0; ks < 8; ks++){
            const int j0 = ks*8 + tig, j1 = j0 + 4;
            const float4 jd0 = jd_s[buf][j0];
            const float4 jd1 = jd_s[buf][j1];
            uint32 a0 = wcalc(f1_0, pq0, jd0, m0.x, m0.y, j0);
            uint32 a1 = wcalc(f1_1, pq1, jd0, m1.x, m1.y, j0);
            uint32 a2 = wcalc(f1_0, pq0, jd1, m0.x, m0.y, j1);
            uint32 a3 = wcalc(f1_1, pq1, jd1, m1.x, m1.y, j1);
            uint32 a4 = wcalc(f1_2, pq2, jd0, m2.x, m2.y, j0);
            uint32 a5 = wcalc(f1_3, pq3, jd0, m3.x, m3.y, j0);
            uint32 a6 = wcalc(f1_2, pq2, jd1, m2.x, m2.y, j1);
            uint32 a7 = wcalc(f1_3, pq3, jd1, m3.x, m3.y, j1);
            const float* hb0 = &h_B[buf][(ks*8 + tig)*HS + g*12];
            const float* hb1 = hb0 + 4*HS;
            float4 pA = *(const float4*)hb0;
            float4 pB = *(const float4*)(hb0 + 4);
            float  pC = hb0[8];
            float4 qA = *(const float4*)hb1;
            float4 qB = *(const float4*)(hb1 + 4);
            float  qC = hb1[8];
            float bl0[9] = {pA.x,pA.y,pA.z,pA.w, pB.x,pB.y,pB.z,pB.w, pC};
            float bl1[9] = {qA.x,qA.y,qA.z,qA.w, qB.x,qB.y,qB.z,qB.w, qC};
#pragma unroll
            for (int nt = 0; nt < 9; nt++){
                uint32 b0 = __float_as_uint(bl0[nt]);
                uint32 b1 = __float_as_uint(bl1[nt]);
                mma_tf32(accA[nt], a0, a1, a2, a3, b0, b1);
                mma_tf32(accB[nt], a4, a5, a6, a7, b0, b1);
            }
        }
        if (more) CP_WAIT0();
        __syncthreads();
        buf ^= 1;
        if (more){ m0 = nm0; m1 = nm1; m2 = nm2; m3 = nm3; }
    }

    float* p0 = partp + (((size_t)head*gridDim.y + blockIdx.y)*NN + rA)*72;
    float* p1 = p0 + 8*72;
    float* p2 = p0 + 16*72;
    float* p3 = p0 + 24*72;
#pragma unroll
    for (int nt = 0; nt < 9; nt++){
        int c = nt*8 + 2*tig;
        if (c < 66){
            p0[c] = accA[nt].x; p1[c] = accA[nt].z;
            p2[c] = accB[nt].x; p3[c] = accB[nt].z;
            if (c + 1 < 66){
                p0[c+1] = accA[nt].y; p1[c+1] = accA[nt].w;
                p2[c+1] = accB[nt].y; p3[c+1] = accB[nt].w;
            }
        }
    }
    if (tig == 1){
        p0[66] = accA[8].x; p1[66] = accA[8].z;
        p2[66] = accB[8].x; p3[66] = accB[8].z;
    }
}

// combine S splits per head: out[row, head*66+c] = lrelu(num/den). blockDim = H*66.
__global__ void reduce_kernel(const float* __restrict__ part, int S,
                              float* __restrict__ out, int os)
{
    int i = blockIdx.x;
    int t = threadIdx.x;
    int h = t/66, c = t - h*66;
    const float* p = part + (((size_t)h*S)*NN + i)*72;
    float num = 0.f, den = 0.f;
    for (int s = 0; s < S; s++){
        num += p[c]; den += p[66];
        p += (size_t)NN*72;
    }
    float v = num/den;
    out[(size_t)i*os + h*66 + c] = fmaxf(v, 0.01f*v);
}

// fused: reduce 16 stage-2 splits -> sub[66] in smem, then value=sigmoid(sub@W+b).
__global__ void __launch_bounds__(128) gate1_fused_kernel(const float* __restrict__ part,
    const float* __restrict__ hx, const float* __restrict__ W, const float* __restrict__ b,
    float* __restrict__ xout, float* __restrict__ uout)
{
    __shared__ float xs[66];
    int i = blockIdx.x, c = threadIdx.x;
    if (c < 66){
        const float* p = part + (size_t)i*72;
        float num = 0.f, den = 0.f;
#pragma unroll
        for (int s = 0; s < 16; s++){
            num += p[c]; den += p[66];
            p += (size_t)NN*72;
        }
        float v = num/den;
        xs[c] = fmaxf(v, 0.01f*v);
    }
    __syncthreads();
    float a = b[c];
    for (int k = 0; k < 66; k++) a += xs[k]*W[k*128+c];
    float v = 1.f/(1.f + __expf(-a));
    if (c < 64) xout[i*66 + 2 + c] = v*hx[i*64+c];
    else uout[i*64 + c - 64] = v;
}

// fused: reduce 16 stage-2 splits -> sub[66], then c=tanh(sub@W+b), out = u*hx + (1-u)*c.
__global__ void __launch_bounds__(128) final_fused_kernel(const float* __restrict__ part,
    const float* __restrict__ hx, const float* __restrict__ u,
    const float* __restrict__ W, const float* __restrict__ b, float* __restrict__ out)
{
    __shared__ float xs[66];
    int i = blockIdx.x, c = threadIdx.x;
    if (c < 66){
        const float* p = part + (size_t)i*72;
        float num = 0.f, den = 0.f;
#pragma unroll
        for (int s = 0; s < 16; s++){
            num += p[c]; den += p[66];
            p += (size_t)NN*72;
        }
        float v = num/den;
        xs[c] = fmaxf(v, 0.01f*v);
    }
    __syncthreads();
    if (c >= 64) return;
    float a = b[c];
    for (int k = 0; k < 66; k++) a += xs[k]*W[k*64+c];
    float t = tanhf(a);
    float uu = u[i*64+c];
    out[i*64+c] = uu*hx[i*64+c] + (1.f - uu)*t;
}

struct Ptrs {
    float *x,*h,*f1,*hcat,*u,*part;
    float2 *pq; float4 *jd; unsigned *mask;
};

static void run_subnet(const Ptrs& P, const float* W, const float* a1, const float* a2,
    const float* Wout, const float* ao1, const float* ao2)
{
    proj_kernel<4,2><<<dim3(32,4), 256>>>(P.x, 66, W, a1, a2, P.h, P.f1, P.pq, P.jd);
    agg_mma_kernel<<<dim3(32,8,4), 128>>>(P.h, P.f1, P.pq, P.jd, P.mask, P.part, 8);
    reduce_kernel<<<NN, 264>>>(P.part, 8, P.hcat, 264);
    proj_kernel<16,2><<<dim3(128,1), 256>>>(P.hcat, 264, Wout, ao1, ao2, P.h, P.f1, P.pq, P.jd);
    agg_mma_kernel<<<dim3(32,16,1), 128>>>(P.h, P.f1, P.pq, P.jd, P.mask, P.part, 4);
}

extern "C" void kernel_launch(void* const* d_in, const int* in_sizes, int n_in,
                              void* d_out, int out_size)
{
    const float* inputs = (const float*)d_in[0];
    const float* hx     = (const float*)d_in[1];
    const int*   adj    = (const int*)d_in[2];
    const float* m1_W   = (const float*)d_in[3];
    const float* m1_a1  = (const float*)d_in[4];
    const float* m1_a2  = (const float*)d_in[5];
    const float* m1_Wo  = (const float*)d_in[6];
    const float* m1_ao1 = (const float*)d_in[7];
    const float* m1_ao2 = (const float*)d_in[8];
    const float* m2_W   = (const float*)d_in[9];
    const float* m2_a1  = (const float*)d_in[10];
    const float* m2_a2  = (const float*)d_in[11];
    const float* m2_Wo  = (const float*)d_in[12];
    const float* m2_ao1 = (const float*)d_in[13];
    const float* m2_ao2 = (const float*)d_in[14];
    const float* g1_W   = (const float*)d_in[15];
    const float* g1_b   = (const float*)d_in[16];
    const float* g2_W   = (const float*)d_in[17];
    const float* g2_b   = (const float*)d_in[18];

    Ptrs P; void* t;
    cudaGetSymbolAddress(&t, g_x);    P.x = (float*)t;
    cudaGetSymbolAddress(&t, g_h);    P.h = (float*)t;
    cudaGetSymbolAddress(&t, g_f1);   P.f1 = (float*)t;
    cudaGetSymbolAddress(&t, g_pq);   P.pq = (float2*)t;
    cudaGetSymbolAddress(&t, g_jd);   P.jd = (float4*)t;
    cudaGetSymbolAddress(&t, g_hcat); P.hcat = (float*)t;
    cudaGetSymbolAddress(&t, g_u);    P.u = (float*)t;
    cudaGetSymbolAddress(&t, g_part); P.part = (float*)t;
    cudaGetSymbolAddress(&t, g_mask); P.mask = (unsigned*)t;

    pack_mask_kernel<<<2048, 256>>>(adj, P.mask);
    build_x1_kernel<<<(NN*66+255)/256, 256>>>(inputs, hx, P.x);
    run_subnet(P, m1_W, m1_a1, m1_a2, m1_Wo, m1_ao1, m1_ao2);
    gate1_fused_kernel<<<NN, 128>>>(P.part, hx, g1_W, g1_b, P.x, P.u);
    run_subnet(P, m2_W, m2_a1, m2_a2, m2_Wo, m2_ao1, m2_ao2);
    final_fused_kernel<<<NN, 128>>>(P.part, hx, P.u, g2_W, g2_b, (float*)d_out);
}